// round 5
// baseline (speedup 1.0000x reference)
#include <cuda_runtime.h>
#include <math.h>
#include <stdint.h>

#define E_TOTAL 500000
#define TM 64
#define NTILES ((E_TOTAL + TM - 1) / TM)   // 7813
#define NCOL 384
#define CDIM 128

// fused weights/bias: cols [0,128)=attn-u path, [128,256)=GeGLU x, [256,384)=GeGLU gate
__device__ float g_W[256 * NCOL];
__device__ float g_c[NCOL];
__device__ int   g_idx64;

// packed f32x2 helpers (sm_103a)
#define FFMA2(d, a, b) asm("fma.rn.f32x2 %0, %1, %2, %0;" : "+l"(d) : "l"(a), "l"(b))
#define UNPACK2(lo, hi, v) asm("mov.b64 {%0, %1}, %2;" : "=f"(lo), "=f"(hi) : "l"(v))

// ---------------------------------------------------------------------------
__global__ void detect_idx_kernel(const int* __restrict__ idx32) {
    if (threadIdx.x == 0) {
        int nz = 0;
        for (int i = 0; i < 256; i++) nz |= idx32[2 * i + 1];
        g_idx64 = (nz == 0) ? 1 : 0;
    }
}

// g_W[k][j] = fused weight; k<128 uses Ws row, else Wt row
__global__ void precompute_W_kernel(const float* __restrict__ Ws, const float* __restrict__ Wt,
                                    const float* __restrict__ Wa1, const float* __restrict__ We) {
    int t = blockIdx.x * blockDim.x + threadIdx.x;
    if (t >= 256 * NCOL) return;
    int k = t / NCOL;
    int j = t % NCOL;
    const float* arow = (k < 128) ? (Ws + k * 128) : (Wt + (k - 128) * 128);
    const int off = (k < 128) ? 0 : 128;
    float sum = 0.f;
    if (j < 128) {
        const float* bcol = Wa1 + off * 128 + j;
        #pragma unroll 4
        for (int m = 0; m < 128; m++) sum = fmaf(arow[m], bcol[m * 128], sum);
    } else {
        const float* bcol = We + off * 256 + (j - 128);
        #pragma unroll 4
        for (int m = 0; m < 128; m++) sum = fmaf(arow[m], bcol[m * 256], sum);
    }
    g_W[k * NCOL + j] = sum;
}

__global__ void precompute_c_kernel(const float* __restrict__ Wa1, const float* __restrict__ We,
                                    const float* __restrict__ bs, const float* __restrict__ bt,
                                    const float* __restrict__ ba1) {
    int j = blockIdx.x * blockDim.x + threadIdx.x;
    if (j >= NCOL) return;
    float s;
    if (j < 128) {
        s = ba1[j];
        for (int m = 0; m < 128; m++)
            s += bs[m] * Wa1[m * 128 + j] + bt[m] * Wa1[(128 + m) * 128 + j];
    } else {
        const int jj = j - 128;
        s = 0.f;
        for (int m = 0; m < 128; m++)
            s += bs[m] * We[m * 256 + jj] + bt[m] * We[(128 + m) * 256 + jj];
    }
    g_c[j] = s;
}

// ---------------------------------------------------------------------------
// Fused kernel: Y[64, 384] = X_tile[64, 256] @ g_W + g_c, then
//   attn = sigmoid(relu(Y[:, :128]) . Wa2 + ba2)     (warp shfl reduction)
//   z    = attn * Y[:, 128:] + be ; GeGLU ; LayerNorm ; store.
// 256 threads = 8 warps (rowg) x 32 lanes (colg); thread = 8 rows x 12 cols
// (3 float4 col-groups at 4*colg + 128*jq). Inner loop is pure FFMA2:
// A duplicated in smem -> broadcast LDS.64 gives (a,a) pairs with zero MOVs;
// B pairs come packed from LDS.128.
// ---------------------------------------------------------------------------
// smem: 98304 (sB) + 32768 (sAd) + 4096 (sC/sWa2/sBe/sGa/sBt) + 512 (idx) = 135680
#define SMEM_BYTES 135680

__global__ void __launch_bounds__(256, 1) fused_kernel(
    const float* __restrict__ emb, const void* __restrict__ eidx,
    const float* __restrict__ Wa2, const float* __restrict__ ba2,
    const float* __restrict__ be, const float* __restrict__ gamma,
    const float* __restrict__ beta, float* __restrict__ out)
{
    extern __shared__ float sm[];
    float* sB   = sm;                    // 64*384 = 24576 floats
    float* sAd  = sB + 64 * NCOL;        // 64k x 64r duplicated: 8192 floats
    float* sC   = sAd + 64 * 128;        // 384
    float* sWa2 = sC + NCOL;             // 128
    float* sBe  = sWa2 + 128;            // 256
    float* sGa  = sBe + 256;             // 128
    float* sBt  = sGa + 128;             // 128
    int*   sSrc = (int*)(sBt + 128);     // 64
    int*   sTgt = sSrc + 64;             // 64

    const int tid = threadIdx.x;
    if (tid < 128) { sWa2[tid] = Wa2[tid]; sGa[tid] = gamma[tid]; sBt[tid] = beta[tid]; }
    sBe[tid] = be[tid];
    for (int i = tid; i < NCOL; i += 256) sC[i] = g_c[i];

    const int e0 = blockIdx.x * TM;
    const int cnt = min(TM, E_TOTAL - e0);
    if (tid < TM) {
        int s = 0, t = 0;
        if (tid < cnt) {
            if (g_idx64) {
                const long long* p = (const long long*)eidx;
                s = (int)p[e0 + tid]; t = (int)p[E_TOTAL + e0 + tid];
            } else {
                const int* p = (const int*)eidx;
                s = p[e0 + tid]; t = p[E_TOTAL + e0 + tid];
            }
        }
        sSrc[tid] = s; sTgt[tid] = t;
    }

    const int rowg = tid >> 5;   // warp id: rows rowg*8 .. +7
    const int colg = tid & 31;   // col base 4*colg (+128*jq)

    unsigned long long acc[8][6];
    #pragma unroll
    for (int i = 0; i < 8; i++) {
        #pragma unroll
        for (int j = 0; j < 6; j++) acc[i][j] = 0ull;
    }

    #pragma unroll 1
    for (int kc = 0; kc < 4; kc++) {
        __syncthreads();
        {   // stream fused-weight chunk [64 x 384] (L2-resident, coalesced)
            const float4* gB = (const float4*)(g_W + kc * 64 * NCOL);
            float4* s4 = (float4*)sB;
            #pragma unroll
            for (int q = 0; q < 24; q++) s4[tid + q * 256] = gB[tid + q * 256];
        }
        {   // gather A chunk, stored DUPLICATED: sAd[kk] holds (x,x) per row
            const int r = tid >> 2, qt = tid & 3;
            const int node = (kc < 2) ? sSrc[r] : sTgt[r];
            const float4* src = (const float4*)(emb + (size_t)node * CDIM + (kc & 1) * 64 + qt * 16);
            float2* sd = (float2*)sAd;
            #pragma unroll
            for (int q = 0; q < 4; q++) {
                float4 v = src[q];
                const int kk = qt * 16 + q * 4;
                sd[(kk + 0) * TM + r] = make_float2(v.x, v.x);
                sd[(kk + 1) * TM + r] = make_float2(v.y, v.y);
                sd[(kk + 2) * TM + r] = make_float2(v.z, v.z);
                sd[(kk + 3) * TM + r] = make_float2(v.w, v.w);
            }
        }
        __syncthreads();
        const unsigned long long* sAd64 = (const unsigned long long*)sAd;
        #pragma unroll 4
        for (int kk = 0; kk < 64; kk++) {
            // broadcast (a,a) pairs — no packing MOVs
            unsigned long long ad[8];
            #pragma unroll
            for (int i = 0; i < 8; i++) ad[i] = sAd64[kk * TM + rowg * 8 + i];
            const float* br = sB + kk * NCOL + colg * 4;
            ulonglong2 b0 = *(const ulonglong2*)br;            // u cols
            ulonglong2 b1 = *(const ulonglong2*)(br + 128);    // x cols
            ulonglong2 b2 = *(const ulonglong2*)(br + 256);    // gate cols
            #pragma unroll
            for (int i = 0; i < 8; i++) {
                FFMA2(acc[i][0], ad[i], b0.x);
                FFMA2(acc[i][1], ad[i], b0.y);
                FFMA2(acc[i][2], ad[i], b1.x);
                FFMA2(acc[i][3], ad[i], b1.y);
                FFMA2(acc[i][4], ad[i], b2.x);
                FFMA2(acc[i][5], ad[i], b2.y);
            }
        }
    }

    // ---- epilogue ----
    const float ba2v = ba2[0];
    const int cb = colg * 4;
    #pragma unroll 1
    for (int i = 0; i < 8; i++) {
        const int r = rowg * 8 + i;
        // attention gate: relu(u) . Wa2 over this thread's 4 u-cols, warp-reduce
        float u0, u1, u2, u3;
        UNPACK2(u0, u1, acc[i][0]);
        UNPACK2(u2, u3, acc[i][1]);
        u0 = fmaxf(u0 + sC[cb + 0], 0.f);
        u1 = fmaxf(u1 + sC[cb + 1], 0.f);
        u2 = fmaxf(u2 + sC[cb + 2], 0.f);
        u3 = fmaxf(u3 + sC[cb + 3], 0.f);
        float part = u0 * sWa2[cb] + u1 * sWa2[cb + 1] + u2 * sWa2[cb + 2] + u3 * sWa2[cb + 3];
        #pragma unroll
        for (int o = 16; o >= 1; o >>= 1)
            part += __shfl_xor_sync(0xffffffffu, part, o);
        const float attn = 1.f / (1.f + expf(-(part + ba2v)));

        // GeGLU
        float x0, x1, x2, x3, g0, g1, g2, g3;
        UNPACK2(x0, x1, acc[i][2]);
        UNPACK2(x2, x3, acc[i][3]);
        UNPACK2(g0, g1, acc[i][4]);
        UNPACK2(g2, g3, acc[i][5]);
        float xv[4] = {x0, x1, x2, x3};
        float gvv[4] = {g0, g1, g2, g3};
        float gv[4];
        #pragma unroll
        for (int q = 0; q < 4; q++) {
            const int m = cb + q;
            const float zx = fmaf(attn, xv[q]  + sC[128 + m], sBe[m]);
            const float zg = fmaf(attn, gvv[q] + sC[256 + m], sBe[128 + m]);
            const float gel = 0.5f * zg * (1.f + erff(zg * 0.70710678118654752f));
            gv[q] = zx * gel;
        }
        // LayerNorm over 128 cols (32 lanes x 4)
        float s1 = gv[0] + gv[1] + gv[2] + gv[3];
        float s2 = gv[0] * gv[0] + gv[1] * gv[1] + gv[2] * gv[2] + gv[3] * gv[3];
        #pragma unroll
        for (int o = 16; o >= 1; o >>= 1) {
            s1 += __shfl_xor_sync(0xffffffffu, s1, o);
            s2 += __shfl_xor_sync(0xffffffffu, s2, o);
        }
        const float mu = s1 * (1.f / 128.f);
        const float var = s2 * (1.f / 128.f) - mu * mu;
        const float rstd = rsqrtf(var + 1e-5f);
        if (r < cnt) {
            float4 o4;
            o4.x = (gv[0] - mu) * rstd * sGa[cb + 0] + sBt[cb + 0];
            o4.y = (gv[1] - mu) * rstd * sGa[cb + 1] + sBt[cb + 1];
            o4.z = (gv[2] - mu) * rstd * sGa[cb + 2] + sBt[cb + 2];
            o4.w = (gv[3] - mu) * rstd * sGa[cb + 3] + sBt[cb + 3];
            *(float4*)(out + (size_t)(e0 + r) * CDIM + cb) = o4;
        }
    }
}

// ---------------------------------------------------------------------------
extern "C" void kernel_launch(void* const* d_in, const int* in_sizes, int n_in,
                              void* d_out, int out_size) {
    const float* emb   = (const float*)d_in[0];
    const void*  eidx  = d_in[1];
    const float* Ws    = (const float*)d_in[2];
    const float* bs    = (const float*)d_in[3];
    const float* Wt    = (const float*)d_in[4];
    const float* bt    = (const float*)d_in[5];
    const float* Wa1   = (const float*)d_in[6];
    const float* ba1   = (const float*)d_in[7];
    const float* Wa2   = (const float*)d_in[8];
    const float* ba2   = (const float*)d_in[9];
    const float* We    = (const float*)d_in[10];
    const float* be    = (const float*)d_in[11];
    const float* gamma = (const float*)d_in[12];
    const float* beta  = (const float*)d_in[13];
    float* out = (float*)d_out;

    cudaFuncSetAttribute(fused_kernel, cudaFuncAttributeMaxDynamicSharedMemorySize, SMEM_BYTES);

    detect_idx_kernel<<<1, 32>>>((const int*)eidx);
    precompute_W_kernel<<<(256 * NCOL + 255) / 256, 256>>>(Ws, Wt, Wa1, We);
    precompute_c_kernel<<<2, 256>>>(Wa1, We, bs, bt, ba1);
    fused_kernel<<<NTILES, 256, SMEM_BYTES>>>(emb, eidx, Wa2, ba2, be, gamma, beta, out);
}